// round 16
// baseline (speedup 1.0000x reference)
#include <cuda_runtime.h>
#include <cstdint>

// Embedding gather: out[r, :] = weight[ids[r], :]
// weight: [50257, 1024] fp32 (4KB/row), ids: [32768] int32, out: [32768,1024] fp32
//
// R16: hybrid read/write engines.
//   READ  path: R13's proven gather front-end — 256 threads, 8 rows/CTA,
//               8 independent float4 LDGs (compiler front-batched, MLP~8).
//   WRITE path: rows base..base+7 are CONTIGUOUS 32KB in the output, so the
//               CTA stages them in SMEM and emits ONE 32KB cp.async.bulk
//               store — a page-sequential DMA burst instead of 512B-granular
//               scattered warp stores. The write stream is the 128MB that is
//               guaranteed DRAM traffic; this gives it optimal shape.
// Thread 0 waits bulk_group.read 0 before exiting so SMEM stays valid for
// the in-flight DMA read; the other 255 threads retire immediately.

#define DIM4 256          // DIM/4 float4 per row
#define THREADS 256
#define ROWS_PER_CTA 8
#define TILE_BYTES (ROWS_PER_CTA * 4096)   // 32KB

__device__ __forceinline__ uint32_t smem_u32(const void* p) {
    uint32_t a;
    asm("{ .reg .u64 t; cvta.to.shared.u64 t, %1; cvt.u32.u64 %0, t; }"
        : "=r"(a) : "l"(p));
    return a;
}

__global__ __launch_bounds__(THREADS)
void embed_gather_kernel(const float4* __restrict__ weight,
                         const int* __restrict__ ids,
                         float4* __restrict__ out,
                         int n_rows)
{
    __shared__ alignas(128) float4 buf[ROWS_PER_CTA * DIM4];  // 32KB

    const int tid  = threadIdx.x;
    const int base = blockIdx.x * ROWS_PER_CTA;

    // 8 independent broadcast index loads (one scoreboard wait)
    int idx[ROWS_PER_CTA];
#pragma unroll
    for (int r = 0; r < ROWS_PER_CTA; r++)
        idx[r] = ids[base + r];

    // 8 independent 16B gathers — compiler front-batched (proven read path)
    float4 v[ROWS_PER_CTA];
#pragma unroll
    for (int r = 0; r < ROWS_PER_CTA; r++)
        v[r] = weight[(size_t)idx[r] * DIM4 + tid];

    // stage rows contiguously in SMEM: row r at buf + r*DIM4
#pragma unroll
    for (int r = 0; r < ROWS_PER_CTA; r++)
        buf[r * DIM4 + tid] = v[r];

    __syncthreads();

    if (tid == 0) {
        // order generic-proxy STS before async-proxy bulk read of SMEM
        asm volatile("fence.proxy.async.shared::cta;" ::: "memory");
        char* dst = (char*)(out + (size_t)base * DIM4);
        uint32_t src = smem_u32(buf);
        asm volatile("cp.async.bulk.global.shared::cta.bulk_group [%0], [%1], %2;"
                     :: "l"(dst), "r"(src), "r"(TILE_BYTES) : "memory");
        asm volatile("cp.async.bulk.commit_group;" ::: "memory");
        // keep SMEM alive until the DMA has read it
        asm volatile("cp.async.bulk.wait_group.read 0;" ::: "memory");
    }
}

extern "C" void kernel_launch(void* const* d_in, const int* in_sizes, int n_in,
                              void* d_out, int out_size)
{
    // Identify inputs by element count:
    //   weight: 50257*1024 = 51463168 elements; ids: 32768 elements
    const float4* weight;
    const int* ids;
    int n_rows;

    if (in_sizes[0] > in_sizes[1]) {
        weight = (const float4*)d_in[0];
        ids    = (const int*)d_in[1];
        n_rows = in_sizes[1];
    } else {
        weight = (const float4*)d_in[1];
        ids    = (const int*)d_in[0];
        n_rows = in_sizes[0];
    }

    int n_blocks = n_rows / ROWS_PER_CTA;  // 32768/8 = 4096, exact
    embed_gather_kernel<<<n_blocks, THREADS>>>(weight, ids, (float4*)d_out, n_rows);
}

// round 17
// speedup vs baseline: 1.0572x; 1.0572x over previous
#include <cuda_runtime.h>
#include <cstdint>

// Embedding gather: out[r, :] = weight[ids[r], :]
// weight: [50257, 1024] fp32, ids: [32768] int32, out: [32768, 1024] fp32
//
// R17: byte-exact revert to the fastest measured kernel (R11, 34.8us,
// DRAM 69.7%, 5519 GB/s):
//   - 8 rows/CTA, 256 threads, one float4 column slot per thread
//   - loads: ld.global.nc + L2::cache_hint evict_last policy (16B gathers,
//     compiler-scheduled)
//   - stores: st.global.wt (write-through — the only cache-op that measurably
//     helped; avoids L2 allocation churn for the 128MB write-once stream)
// Structural alternatives all measured slower: forced-MLP asm (37.0us),
// 256-bit loads (41.2), bulk-DMA round trip (38.0), SMEM-staged 32KB bulk
// stores (39.6). ~35us @ ~190MB is this chip's mixed-stream ceiling.

#define DIM4 256          // DIM/4 float4 per row
#define THREADS 256
#define ROWS_PER_CTA 8

__global__ __launch_bounds__(THREADS)
void embed_gather_kernel(const float4* __restrict__ weight,
                         const int* __restrict__ ids,
                         float4* __restrict__ out,
                         int n_rows)
{
    const int tid  = threadIdx.x;
    const int base = blockIdx.x * ROWS_PER_CTA;

    // L2 policy: evict_last for the gathered weight rows
    uint64_t policy;
    asm("createpolicy.fractional.L2::evict_last.b64 %0, 1.0;" : "=l"(policy));

    // 8 independent broadcast index loads
    int idx[ROWS_PER_CTA];
#pragma unroll
    for (int r = 0; r < ROWS_PER_CTA; r++)
        idx[r] = ids[base + r];

    // 8 independent 16B gathers with evict_last cache hint
    float v[ROWS_PER_CTA][4];
#pragma unroll
    for (int r = 0; r < ROWS_PER_CTA; r++) {
        const float4* src = weight + (size_t)idx[r] * DIM4 + tid;
        asm("ld.global.nc.L2::cache_hint.v4.f32 {%0, %1, %2, %3}, [%4], %5;"
            : "=f"(v[r][0]), "=f"(v[r][1]), "=f"(v[r][2]), "=f"(v[r][3])
            : "l"(src), "l"(policy));
    }

    // 8 write-through stores: no L2 allocation for the write-once output
#pragma unroll
    for (int r = 0; r < ROWS_PER_CTA; r++) {
        float4* dst = out + (size_t)(base + r) * DIM4 + tid;
        asm volatile("st.global.wt.v4.f32 [%0], {%1, %2, %3, %4};"
                     :: "l"(dst),
                        "f"(v[r][0]), "f"(v[r][1]), "f"(v[r][2]), "f"(v[r][3])
                     : "memory");
    }
}

extern "C" void kernel_launch(void* const* d_in, const int* in_sizes, int n_in,
                              void* d_out, int out_size)
{
    // Identify inputs by element count:
    //   weight: 50257*1024 = 51463168 elements; ids: 32768 elements
    const float4* weight;
    const int* ids;
    int n_rows;

    if (in_sizes[0] > in_sizes[1]) {
        weight = (const float4*)d_in[0];
        ids    = (const int*)d_in[1];
        n_rows = in_sizes[1];
    } else {
        weight = (const float4*)d_in[1];
        ids    = (const int*)d_in[0];
        n_rows = in_sizes[0];
    }

    int n_blocks = n_rows / ROWS_PER_CTA;  // 32768/8 = 4096, exact
    embed_gather_kernel<<<n_blocks, THREADS>>>(weight, ids, (float4*)d_out, n_rows);
}